// round 1
// baseline (speedup 1.0000x reference)
#include <cuda_runtime.h>

#define DNUM 20
#define ONUM 19
#define MNUM 32
#define PJ   36                     // padded row stride (floats) for conflict-free LDS.128
#define NPAIR (ONUM * ONUM)         // 361 (c,d) pairs per (a,b)
#define WARPS 12
#define THREADS (WARPS * 32)
#define HALVES 2
#define CSLAB (MNUM * PJ)           // floats per k-slab of C = 1152
#define CSLAB4 (CSLAB / 4)          // 288 float4 per slab

// Cosine table C[k][i][j] (padded j to 36), k in [0,19): cos(2*pi*k / (32*i + j + 2))
__device__ __align__(16) float g_C[ONUM * CSLAB];

__global__ void init_tabs() {
    int t = blockIdx.x * blockDim.x + threadIdx.x;
    if (t < ONUM * CSLAB) {
        int k = t / CSLAB;
        int r = t % CSLAB;
        int i = r / PJ;
        int j = r % PJ;
        float v = 0.0f;
        if (j < MNUM) {
            float period = (float)(i * MNUM + j + 2);
            v = cosf(6.283185307179586f * (float)k / period);
        }
        g_C[t] = v;
    }
}

__global__ __launch_bounds__(THREADS, 2)
void sdd_main(const float* __restrict__ h, const float* __restrict__ Mw,
              const float* __restrict__ P, float* __restrict__ out) {
    __shared__ __align__(16) float sWab[MNUM * PJ];   // P * C[a] * C[b], padded
    __shared__ __align__(16) float sM[MNUM * PJ];     // M_w rows, padded
    __shared__ __align__(16) float sWin[WARPS * MNUM];
    __shared__ __align__(16) float sX[WARPS * MNUM];

    const int tid = threadIdx.x;
    const int ab = blockIdx.x >> 1;
    const int half = blockIdx.x & 1;
    const int a = ab / ONUM, b = ab % ONUM;

    // Block setup: stage M rows (padded) and Wab = P .* C[a] .* C[b]
    for (int t = tid; t < MNUM * MNUM; t += THREADS) {
        int i = t >> 5, j = t & 31;
        sM[i * PJ + j] = Mw[t];
        sWab[i * PJ + j] = P[t] * g_C[a * CSLAB + i * PJ + j]
                                * g_C[b * CSLAB + i * PJ + j];
    }
    __syncthreads();

    const int w = tid >> 5, lane = tid & 31;
    const int slot = half * WARPS + w;
    const int p0 = (NPAIR * slot) / (WARPS * HALVES);
    const int p1 = (NPAIR * (slot + 1)) / (WARPS * HALVES);

    float tmp[32];                 // Wab[lane,j] * C[c,lane,j], lane = output index i
    int c_cur = -1;
    int d_prev = -1000;
    float cs_next = 0.0f;

    float* sWinW = sWin + w * MNUM;
    float* sXW   = sX   + w * MNUM;
    const float4* C4 = (const float4*)g_C;
    const float4* W4 = (const float4*)sWab;
    const float4* Mr4 = (const float4*)sM + lane * (PJ / 4);

    for (int p = p0; p < p1; ++p) {
        const int c = p / ONUM, d = p % ONUM;

        if (c != c_cur) {
            c_cur = c;
            d_prev = -1000;
            const float4* Cc4 = C4 + c * CSLAB4 + lane * (PJ / 4);
            #pragma unroll
            for (int jv = 0; jv < 8; ++jv) {
                float4 wv = W4[lane * (PJ / 4) + jv];
                float4 cv = __ldg(Cc4 + jv);
                tmp[4 * jv + 0] = wv.x * cv.x;
                tmp[4 * jv + 1] = wv.y * cv.y;
                tmp[4 * jv + 2] = wv.z * cv.z;
                tmp[4 * jv + 3] = wv.w * cv.w;
            }
        }

        // colsum(d') = sum over {da,db,dc} of h[a+da, b+db, c+dc, d', lane]
        const float* hb = h + ((((a * DNUM + b) * DNUM + c) * DNUM) + d) * MNUM + lane;
        // offsets (floats): da -> 256000, db -> 12800, dc -> 640, d step -> 32
        float cs0, cs1;
        if (d == d_prev + 1) {
            cs0 = cs_next;
        } else {
            const float* q = hb;
            cs0 = __ldg(q) + __ldg(q + 640) + __ldg(q + 12800) + __ldg(q + 13440)
                + __ldg(q + 256000) + __ldg(q + 256640)
                + __ldg(q + 268800) + __ldg(q + 269440);
        }
        {
            const float* q = hb + MNUM;
            cs1 = __ldg(q) + __ldg(q + 640) + __ldg(q + 12800) + __ldg(q + 13440)
                + __ldg(q + 256000) + __ldg(q + 256640)
                + __ldg(q + 268800) + __ldg(q + 269440);
        }
        cs_next = cs1;
        d_prev = d;
        const float win = (cs0 + cs1) * 0.0625f;

        // matvec: x_j = sum_k M_w[j,k] * win_k   (lane = j)
        __syncwarp();
        sWinW[lane] = win;
        __syncwarp();
        float x = 0.0f;
        const float4* Wn4 = (const float4*)sWinW;
        #pragma unroll
        for (int kv = 0; kv < 8; ++kv) {
            float4 mv = Mr4[kv];
            float4 wv = Wn4[kv];
            x = fmaf(mv.x, wv.x, x);
            x = fmaf(mv.y, wv.y, x);
            x = fmaf(mv.z, wv.z, x);
            x = fmaf(mv.w, wv.w, x);
        }
        __syncwarp();
        sXW[lane] = x;
        __syncwarp();

        // Nk_i = sum_j x_j * (P*Ca*Cb*Cc)[i,j] * C[d,i,j]   (lane = i)
        float acc = 0.0f;
        const float4* Cd4 = C4 + d * CSLAB4 + lane * (PJ / 4);
        const float4* X4 = (const float4*)sXW;
        #pragma unroll
        for (int jv = 0; jv < 8; ++jv) {
            float4 cv = __ldg(Cd4 + jv);
            float4 xv = X4[jv];
            acc = fmaf(xv.x * tmp[4 * jv + 0], cv.x, acc);
            acc = fmaf(xv.y * tmp[4 * jv + 1], cv.y, acc);
            acc = fmaf(xv.z * tmp[4 * jv + 2], cv.z, acc);
            acc = fmaf(xv.w * tmp[4 * jv + 3], cv.w, acc);
        }

        out[(((((a * ONUM + b) * ONUM + c) * ONUM) + d) << 5) + lane] = acc;
    }
}

extern "C" void kernel_launch(void* const* d_in, const int* in_sizes, int n_in,
                              void* d_out, int out_size) {
    const float* h  = (const float*)d_in[0];   // hypervol [20,20,20,20,32]
    const float* Mw = (const float*)d_in[1];   // M_w [32,32]
    const float* P  = (const float*)d_in[2];   // P [32,32]
    float* out = (float*)d_out;                // [130321, 32]

    const int tot = ONUM * CSLAB;
    init_tabs<<<(tot + 511) / 512, 512>>>();
    sdd_main<<<NPAIR * HALVES, THREADS>>>(h, Mw, P, out);
}